// round 16
// baseline (speedup 1.0000x reference)
#include <cuda_runtime.h>
#include <cuda_fp16.h>
#include <cstdint>
#include <math.h>

#define Bsz 4096
#define Ff  1024
#define Ee  16
#define Dd  8
#define Tt  1040
#define Ll  3
#define K1P 1088   // padded K for layer 1 (multiple of 64)

// ---------------- scratch (device globals; no allocation allowed) ----------
__device__ __align__(128) __half g_xc [Bsz*K1P];
__device__ __align__(128) __half g_ch1[Bsz*512];
__device__ __align__(128) __half g_dg1[Bsz*512];
__device__ __align__(128) __half g_hd [Bsz*128];
__device__ __align__(128) __half g_wh1c[K1P*512];
__device__ __align__(128) __half g_wh1d[Dd*K1P*512];
__device__ __align__(128) __half g_wh2c[512*256];
__device__ __align__(128) __half g_wh2d[Dd*512*256];
__device__ __align__(128) __half g_wh3c[256*128];
__device__ __align__(128) __half g_wh3d[Dd*256*128];
__device__ float g_aux[Bsz];
__device__ int   g_cnt[Dd];
__device__ int   g_off[Dd];
__device__ int   g_perm[Bsz];
__device__ int   g_flag[Bsz];

// ---------------- PTX helpers ----------------------------------------------
__device__ __forceinline__ uint32_t smem_u32(const void* p) {
    uint32_t a;
    asm("{ .reg .u64 t; cvta.to.shared.u64 t, %1; cvt.u32.u64 %0, t; }" : "=r"(a) : "l"(p));
    return a;
}
__device__ __forceinline__ void ldsm4(uint32_t* r, uint32_t addr) {
    asm volatile("ldmatrix.sync.aligned.m8n8.x4.shared.b16 {%0,%1,%2,%3}, [%4];"
        : "=r"(r[0]), "=r"(r[1]), "=r"(r[2]), "=r"(r[3]) : "r"(addr));
}
__device__ __forceinline__ void ldsm4t(uint32_t* r, uint32_t addr) {
    asm volatile("ldmatrix.sync.aligned.m8n8.x4.trans.shared.b16 {%0,%1,%2,%3}, [%4];"
        : "=r"(r[0]), "=r"(r[1]), "=r"(r[2]), "=r"(r[3]) : "r"(addr));
}
__device__ __forceinline__ void mma_f16(float* c, const uint32_t* a, const uint32_t* b) {
    asm volatile("mma.sync.aligned.m16n8k16.row.col.f32.f16.f16.f32 "
        "{%0,%1,%2,%3}, {%4,%5,%6,%7}, {%8,%9}, {%0,%1,%2,%3};"
        : "+f"(c[0]), "+f"(c[1]), "+f"(c[2]), "+f"(c[3])
        : "r"(a[0]), "r"(a[1]), "r"(a[2]), "r"(a[3]), "r"(b[0]), "r"(b[1]));
}
__device__ __forceinline__ void cpa16(uint32_t dst, const void* src) {
    asm volatile("cp.async.cg.shared.global [%0], [%1], 16;" :: "r"(dst), "l"(src) : "memory");
}
#define CPA_COMMIT() asm volatile("cp.async.commit_group;" ::: "memory")
#define CPA_WAIT1()  asm volatile("cp.async.wait_group 1;" ::: "memory")
#define CPA_WAIT2()  asm volatile("cp.async.wait_group 2;" ::: "memory")
#define CPA_WAIT0()  asm volatile("cp.async.wait_group 0;" ::: "memory")

// ---------------- block reduce ----------------------------------------------
__device__ __forceinline__ float blockReduceSum256(float v, float* red) {
    int tid = threadIdx.x;
    #pragma unroll
    for (int o = 16; o; o >>= 1) v += __shfl_down_sync(0xffffffffu, v, o);
    if ((tid & 31) == 0) red[tid >> 5] = v;
    __syncthreads();
    if (tid < 32) {
        float x = (tid < 8) ? red[tid] : 0.f;
        #pragma unroll
        for (int o = 4; o; o >>= 1) x += __shfl_down_sync(0xffffffffu, x, o);
        if (tid == 0) red[0] = x;
    }
    __syncthreads();
    float r = red[0];
    __syncthreads();
    return r;
}

// ---------------- k_front: prep rows + weight convert + partition -----------
#define CVT_TOTAL 6488064
#define CVT_BLOCKS 3168
#define FRONT_BLOCKS (Bsz + CVT_BLOCKS + 1)

__global__ __launch_bounds__(256)
void k_front(const float* __restrict__ x, const int* __restrict__ dom,
             const float* __restrict__ pnw, const float* __restrict__ pnb,
             const float* __restrict__ demb,
             const float* __restrict__ cw, const float* __restrict__ cb,
             const float* __restrict__ aW1, const float* __restrict__ ab1,
             const float* __restrict__ aW2, const float* __restrict__ ab2,
             const float* __restrict__ cW1, const float* __restrict__ dW1,
             const float* __restrict__ cW2, const float* __restrict__ dW2,
             const float* __restrict__ cW3, const float* __restrict__ dW3)
{
    const int bid = blockIdx.x;
    const int tid = threadIdx.x;

    if (bid >= Bsz) {
        if (bid == Bsz + CVT_BLOCKS) {
            __shared__ int scnt[Dd], soff[Dd], scur[Dd];
            if (tid < Dd) { scnt[tid] = 0; scur[tid] = 0; }
            __syncthreads();
            int dv[16];
            #pragma unroll
            for (int i = 0; i < 16; i++) {
                dv[i] = dom[tid + 256 * i];
                g_flag[tid + 256 * i] = 0;
                atomicAdd(&scnt[dv[i]], 1);
            }
            __syncthreads();
            if (tid == 0) {
                int s = 0;
                for (int d = 0; d < Dd; d++) { soff[d] = s; g_off[d] = s; g_cnt[d] = scnt[d]; s += scnt[d]; }
            }
            __syncthreads();
            #pragma unroll
            for (int i = 0; i < 16; i++) {
                int p = atomicAdd(&scur[dv[i]], 1);
                g_perm[soff[dv[i]] + p] = tid + 256 * i;
            }
            return;
        }
        size_t idx = ((size_t)(bid - Bsz) * 256 + tid) * 8;
        const float* src; __half* dst;
        int KIN, KPAD, N;
        size_t off;
        if      (idx < 557056)  { src = cW1; dst = g_wh1c; KIN = Tt;  KPAD = K1P; N = 512; off = idx; }
        else if (idx < 5013504) { src = dW1; dst = g_wh1d; KIN = Tt;  KPAD = K1P; N = 512; off = idx - 557056; }
        else if (idx < 5144576) { src = cW2; dst = g_wh2c; KIN = 512; KPAD = 512; N = 256; off = idx - 5013504; }
        else if (idx < 6193152) { src = dW2; dst = g_wh2d; KIN = 512; KPAD = 512; N = 256; off = idx - 5144576; }
        else if (idx < 6225920) { src = cW3; dst = g_wh3c; KIN = 256; KPAD = 256; N = 128; off = idx - 6193152; }
        else                    { src = dW3; dst = g_wh3d; KIN = 256; KPAD = 256; N = 128; off = idx - 6225920; }

        size_t per = (size_t)KPAD * N;
        int d = (int)(off / per);
        size_t r = off % per;
        int k = (int)(r / N), n = (int)(r % N);
        uint4 u;
        if (k < KIN) {
            const float* s = src + ((size_t)d * KIN + k) * N + n;
            float4 f0 = *(const float4*)s;
            float4 f1 = *(const float4*)(s + 4);
            __half2 h0 = __floats2half2_rn(f0.x, f0.y), h1 = __floats2half2_rn(f0.z, f0.w);
            __half2 h2 = __floats2half2_rn(f1.x, f1.y), h3 = __floats2half2_rn(f1.z, f1.w);
            u.x = *(uint32_t*)&h0; u.y = *(uint32_t*)&h1;
            u.z = *(uint32_t*)&h2; u.w = *(uint32_t*)&h3;
        } else {
            u = make_uint4(0, 0, 0, 0);
        }
        *(uint4*)(dst + off) = u;
        return;
    }

    // ---- prep (vectorized) ----
    __shared__ __align__(16) float s_x0[Tt];
    __shared__ __align__(16) float s_xc[Tt];
    __shared__ float red[32];

    const int r = bid;
    const float* xr = x + (size_t)r * Ff;
    const int j4 = tid * 4;

    float4 xv = *(const float4*)(xr + j4);
    float sum = xv.x + xv.y + xv.z + xv.w;
    float sq  = xv.x * xv.x + xv.y * xv.y + xv.z * xv.z + xv.w * xv.w;
    float tot  = blockReduceSum256(sum, red);
    float tot2 = blockReduceSum256(sq, red);
    float mean = tot * (1.f / Ff);
    float var  = tot2 * (1.f / Ff) - mean * mean;
    float rstd = rsqrtf(var + 1e-5f);

    int d = dom[r];
    {
        const float* wr = pnw + (size_t)d * Ff;
        const float* br = pnb + (size_t)d * Ff;
        float4 wv = *(const float4*)(wr + j4);
        float4 bv = *(const float4*)(br + j4);
        float4 nv;
        nv.x = (xv.x - mean) * rstd * wv.x + bv.x;
        nv.y = (xv.y - mean) * rstd * wv.y + bv.y;
        nv.z = (xv.z - mean) * rstd * wv.z + bv.z;
        nv.w = (xv.w - mean) * rstd * wv.w + bv.w;
        *(float4*)(s_x0 + j4) = nv;
        *(float4*)(s_xc + j4) = nv;
    }
    if (tid < Ee) {
        float v = demb[d * Ee + tid];
        s_x0[Ff + tid] = v;
        s_xc[Ff + tid] = v;
    }
    __syncthreads();

    #pragma unroll
    for (int i = 0; i < Ll; i++) {
        const float* wi = cw + i * Tt;
        const float* bi = cb + i * Tt;
        float p;
        {
            float4 a = *(const float4*)(s_xc + j4);
            float4 w = *(const float4*)(wi + j4);
            p = a.x * w.x + a.y * w.y + a.z * w.z + a.w * w.w;
            if (tid < 4) {
                int jt = Ff + tid * 4;
                float4 a2 = *(const float4*)(s_xc + jt);
                float4 w2 = *(const float4*)(wi + jt);
                p += a2.x * w2.x + a2.y * w2.y + a2.z * w2.z + a2.w * w2.w;
            }
        }
        float proj = blockReduceSum256(p, red);
        {
            float4 x0v = *(const float4*)(s_x0 + j4);
            float4 bv  = *(const float4*)(bi + j4);
            float4 xcv = *(const float4*)(s_xc + j4);
            xcv.x = fmaf(x0v.x, proj, bv.x + xcv.x);
            xcv.y = fmaf(x0v.y, proj, bv.y + xcv.y);
            xcv.z = fmaf(x0v.z, proj, bv.z + xcv.z);
            xcv.w = fmaf(x0v.w, proj, bv.w + xcv.w);
            *(float4*)(s_xc + j4) = xcv;
            if (tid < 4) {
                int jt = Ff + tid * 4;
                float4 x0t = *(const float4*)(s_x0 + jt);
                float4 bt  = *(const float4*)(bi + jt);
                float4 xct = *(const float4*)(s_xc + jt);
                xct.x = fmaf(x0t.x, proj, bt.x + xct.x);
                xct.y = fmaf(x0t.y, proj, bt.y + xct.y);
                xct.z = fmaf(x0t.z, proj, bt.z + xct.z);
                xct.w = fmaf(x0t.w, proj, bt.w + xct.w);
                *(float4*)(s_xc + jt) = xct;
            }
        }
        __syncthreads();
    }

    __half* outp = g_xc + (size_t)r * K1P;
    {
        float4 v = *(const float4*)(s_xc + j4);
        __half2 h0 = __floats2half2_rn(v.x, v.y), h1 = __floats2half2_rn(v.z, v.w);
        uint2 u; u.x = *(uint32_t*)&h0; u.y = *(uint32_t*)&h1;
        *(uint2*)(outp + j4) = u;
        if (tid < 4) {
            int jt = Ff + tid * 4;
            float4 vt = *(const float4*)(s_xc + jt);
            __half2 t0 = __floats2half2_rn(vt.x, vt.y), t1 = __floats2half2_rn(vt.z, vt.w);
            uint2 ut; ut.x = *(uint32_t*)&t0; ut.y = *(uint32_t*)&t1;
            *(uint2*)(outp + jt) = ut;
        }
        if (tid < (K1P - Tt)) outp[Tt + tid] = __float2half_rn(0.f);
    }

    if (tid < 32) {
        float s = ab1[tid];
        #pragma unroll
        for (int e = 0; e < Ee; e++) s = fmaf(s_x0[Ff + e], aW1[e * 32 + tid], s);
        s = fmaxf(s, 0.f) * aW2[tid];
        #pragma unroll
        for (int o = 16; o; o >>= 1) s += __shfl_down_sync(0xffffffffu, s, o);
        if (tid == 0) g_aux[r] = s + ab2[0];
    }
}

// ---------------- layer-1 GEMM (8 warps, 64x32 tiles, BK=64, 3 stages) ------
#define BK     64
#define LDH    72
#define LDB    136
#define ASZ    (128*LDH)
#define BSZ    (BK*LDB)
#define STAGES 3
#define DYNSM  (STAGES*(ASZ+BSZ)*2)   // 107520 bytes

template<int K, int N, bool RELU, int LAYER>
__global__ __launch_bounds__(256, 2)
void gemm_f16(const __half* __restrict__ Ac, const __half* __restrict__ Ad,
              const __half* __restrict__ Wc, const __half* __restrict__ Wd,
              const float* __restrict__ bc, const float* __restrict__ bd,
              __half* __restrict__ Cc, __half* __restrict__ Cd)
{
    extern __shared__ __align__(16) __half tiles[];
    __shared__ int rowA[128], rowC[128];

    const int z  = blockIdx.z;
    const int n0 = blockIdx.x * 128;
    const int m0 = blockIdx.y * 128;

    const __half *A, *W;
    const float* bias;
    __half* C;
    int cnt;
    if (z == 0) { A = Ac; W = Wc; bias = bc; C = Cc; cnt = Bsz; }
    else {
        int d = z - 1;
        cnt = g_cnt[d];
        if (m0 >= cnt) return;
        A = Ad; W = Wd + (size_t)d * K * N; bias = bd + d * N; C = Cd;
    }

    const int tid  = threadIdx.x;
    const int wid  = tid >> 5;
    const int lane = tid & 31;

    if (tid < 128) {
        if (z == 0) { rowA[tid] = m0 + tid; rowC[tid] = m0 + tid; }
        else {
            int off = g_off[z - 1];
            int mm  = min(m0 + tid, cnt - 1);
            int slot = off + mm;
            if (LAYER == 1)      { rowA[tid] = g_perm[slot]; rowC[tid] = slot; }
            else if (LAYER == 2) { rowA[tid] = slot;         rowC[tid] = slot; }
            else                 { rowA[tid] = slot;         rowC[tid] = g_perm[slot]; }
        }
    }
    __syncthreads();

    const __half* aSrc[4];
    const __half* bSrc[4];
    uint32_t aDst[4], bDst[4];
    #pragma unroll
    for (int i = 0; i < 4; i++) {
        int s  = tid + 256 * i;
        int ar = s >> 3, ac8 = (s & 7) * 8;
        aSrc[i] = A + (size_t)rowA[ar] * K + ac8;
        aDst[i] = (uint32_t)(ar * LDH + ac8) * 2;
        int kr = s >> 4, nc8 = (s & 15) * 8;
        bSrc[i] = W + (size_t)kr * N + n0 + nc8;
        bDst[i] = (uint32_t)(kr * LDB + nc8) * 2;
    }

    const uint32_t sbase = smem_u32(tiles);

    const int wm = (wid & 1) * 64;
    const int wn = (wid >> 1) * 32;
    const int gid = lane >> 2, tig = lane & 3;
    const uint32_t aRowOff = (uint32_t)((wm + (lane & 15)) * LDH + ((lane >> 4) * 8)) * 2;
    const uint32_t bAddrOff = (uint32_t)(((lane & 7) + ((lane >> 3) & 1) * 8) * LDB
                                         + wn + (lane >> 4) * 8) * 2;

    float acc[4][4][4];
    #pragma unroll
    for (int mt = 0; mt < 4; mt++)
        #pragma unroll
        for (int nt = 0; nt < 4; nt++)
            #pragma unroll
            for (int i = 0; i < 4; i++) acc[mt][nt][i] = 0.f;

    const int NCH = K / BK;

    auto issue = [&](int c, int st) {
        uint32_t aS = sbase + (uint32_t)(st * ASZ) * 2;
        uint32_t bS = sbase + (uint32_t)(STAGES * ASZ + st * BSZ) * 2;
        int k0 = c * BK;
        #pragma unroll
        for (int i = 0; i < 4; i++) cpa16(aS + aDst[i], aSrc[i] + k0);
        #pragma unroll
        for (int i = 0; i < 4; i++) cpa16(bS + bDst[i], bSrc[i] + (size_t)k0 * N);
    };

    issue(0, 0); CPA_COMMIT();
    issue(1, 1); CPA_COMMIT();

    for (int c = 0; c < NCH; c++) {
        CPA_WAIT1();
        __syncthreads();
        if (c + 2 < NCH) issue(c + 2, (c + 2) % STAGES);
        CPA_COMMIT();

        const int st = c % STAGES;
        const uint32_t aB = sbase + (uint32_t)(st * ASZ) * 2;
        const uint32_t bB = sbase + (uint32_t)(STAGES * ASZ + st * BSZ) * 2;
        #pragma unroll
        for (int kk = 0; kk < BK; kk += 16) {
            uint32_t af[4][4];
            #pragma unroll
            for (int mt = 0; mt < 4; mt++)
                ldsm4(af[mt], aB + aRowOff + (uint32_t)(mt * 16 * LDH + kk) * 2);
            #pragma unroll
            for (int ntp = 0; ntp < 2; ntp++) {
                uint32_t bf[4];
                ldsm4t(bf, bB + bAddrOff + (uint32_t)(kk * LDB + ntp * 16) * 2);
                #pragma unroll
                for (int mt = 0; mt < 4; mt++) {
                    mma_f16(acc[mt][ntp * 2 + 0], af[mt], bf + 0);
                    mma_f16(acc[mt][ntp * 2 + 1], af[mt], bf + 2);
                }
            }
        }
    }
    __syncthreads();

    __half* stage = tiles;
    #pragma unroll
    for (int mt = 0; mt < 4; mt++) {
        #pragma unroll
        for (int nt = 0; nt < 4; nt++) {
            int col = wn + nt * 8 + 2 * tig;
            float bx = bias[n0 + col], by = bias[n0 + col + 1];
            float v0 = acc[mt][nt][0] + bx, v1 = acc[mt][nt][1] + by;
            float v2 = acc[mt][nt][2] + bx, v3 = acc[mt][nt][3] + by;
            if (RELU) {
                v0 = fmaxf(v0, 0.f); v1 = fmaxf(v1, 0.f);
                v2 = fmaxf(v2, 0.f); v3 = fmaxf(v3, 0.f);
            }
            int r0 = wm + mt * 16 + gid;
            *(__half2*)&stage[r0 * 136 + col]       = __floats2half2_rn(v0, v1);
            *(__half2*)&stage[(r0 + 8) * 136 + col] = __floats2half2_rn(v2, v3);
        }
    }
    __syncthreads();
    #pragma unroll
    for (int i = 0; i < 8; i++) {
        int idx = tid + 256 * i;
        int r = idx >> 4, c8 = (idx & 15) * 8;
        if (z == 0 || m0 + r < cnt) {
            uint4 v = *(uint4*)&stage[r * 136 + c8];
            *(uint4*)&C[(size_t)rowC[r] * N + n0 + c8] = v;
        }
    }
}

// ---------------- fused layers 2+3 + STAR fusion + final MLP ----------------
// z = 0..7 : domain nets (launch first) -> write g_hd, set per-row flags
// z = 8    : center -> hc kept in smem, spin on flags, compute final output
#define BK2   32
#define LDH2  40
#define LDB2  264
#define LDT   264
#define LDW3  136
#define A2SZ  (64*LDH2)
#define B2SZ  (BK2*LDB2)
#define ST2   4
#define OFF_T   (ST2*A2SZ + ST2*B2SZ)        // 44032 halfs
#define OFF_W3  (OFF_T + 64*LDT)             // 60928
#define DYNSM23 ((OFF_W3 + 256*LDW3) * 2)    // 191488

__global__ __launch_bounds__(256)
void gemm23(const __half* __restrict__ Ac, const __half* __restrict__ Ad,
            const __half* __restrict__ W2c, const __half* __restrict__ W2d,
            const float* __restrict__ b2c, const float* __restrict__ b2d,
            const __half* __restrict__ W3c, const __half* __restrict__ W3d,
            const float* __restrict__ b3c, const float* __restrict__ b3d,
            __half* __restrict__ Cd,
            const float* __restrict__ fW1, const float* __restrict__ fb1,
            const float* __restrict__ fW2, const float* __restrict__ fb2,
            float* __restrict__ out)
{
    extern __shared__ __align__(16) __half tiles[];
    __shared__ int rowA[64], rowC[64];

    const int z  = blockIdx.z;
    const bool center = (z == Dd);
    const int m0 = blockIdx.y * 64;

    const __half *A, *W2, *W3;
    const float *b2, *b3;
    int cnt;
    if (center) { A = Ac; W2 = W2c; b2 = b2c; W3 = W3c; b3 = b3c; cnt = Bsz; }
    else {
        int d = z;
        cnt = g_cnt[d];
        if (m0 >= cnt) return;
        A  = Ad;
        W2 = W2d + (size_t)d * 512 * 256; b2 = b2d + d * 256;
        W3 = W3d + (size_t)d * 256 * 128; b3 = b3d + d * 128;
    }

    const int tid  = threadIdx.x;
    const int wid  = tid >> 5;
    const int lane = tid & 31;

    if (tid < 64) {
        if (center) { rowA[tid] = m0 + tid; rowC[tid] = m0 + tid; }
        else {
            int off = g_off[z];
            int mm  = min(m0 + tid, cnt - 1);
            int slot = off + mm;
            rowA[tid] = slot;
            rowC[tid] = g_perm[slot];
        }
    }
    __syncthreads();

    const uint32_t sbase = smem_u32(tiles);

    // W3 preload
    {
        uint32_t w3S = sbase + (uint32_t)OFF_W3 * 2;
        #pragma unroll
        for (int i = 0; i < 16; i++) {
            int s = tid + 256 * i;
            int kr = s >> 4, nc8 = (s & 15) * 8;
            cpa16(w3S + (uint32_t)(kr * LDW3 + nc8) * 2, W3 + (size_t)kr * 128 + nc8);
        }
        CPA_COMMIT();
    }

    const __half* aSrc = A + (size_t)rowA[tid >> 2] * 512 + (tid & 3) * 8;
    const uint32_t aDst = (uint32_t)((tid >> 2) * LDH2 + (tid & 3) * 8) * 2;
    const __half* bSrc[4];
    uint32_t bDst[4];
    #pragma unroll
    for (int i = 0; i < 4; i++) {
        int s = tid + 256 * i;
        int kr = s >> 5, nc8 = (s & 31) * 8;
        bSrc[i] = W2 + (size_t)kr * 256 + nc8;
        bDst[i] = (uint32_t)(kr * LDB2 + nc8) * 2;
    }

    auto issue = [&](int c, int st) {
        uint32_t aS = sbase + (uint32_t)(st * A2SZ) * 2;
        uint32_t bS = sbase + (uint32_t)(ST2 * A2SZ + st * B2SZ) * 2;
        int k0 = c * BK2;
        cpa16(aS + aDst, aSrc + k0);
        #pragma unroll
        for (int i = 0; i < 4; i++) cpa16(bS + bDst[i], bSrc[i] + (size_t)k0 * 256);
    };

    issue(0, 0); CPA_COMMIT();
    issue(1, 1); CPA_COMMIT();
    issue(2, 2); CPA_COMMIT();

    const int wm = (wid & 1) * 32;
    const int wn = (wid >> 1) * 64;
    const int gid = lane >> 2, tig = lane & 3;
    const uint32_t aRowOff = (uint32_t)((wm + (lane & 15)) * LDH2 + ((lane >> 4) * 8)) * 2;
    const uint32_t bAddrOff = (uint32_t)(((lane & 7) + ((lane >> 3) & 1) * 8) * LDB2
                                         + wn + (lane >> 4) * 8) * 2;

    float acc[2][8][4];
    #pragma unroll
    for (int mt = 0; mt < 2; mt++)
        #pragma unroll
        for (int nt = 0; nt < 8; nt++)
            #pragma unroll
            for (int i = 0; i < 4; i++) acc[mt][nt][i] = 0.f;

    const int NCH = 512 / BK2;
    for (int c = 0; c < NCH; c++) {
        CPA_WAIT2();
        __syncthreads();
        if (c + 3 < NCH) issue(c + 3, (c + 3) % ST2);
        CPA_COMMIT();

        const int st = c % ST2;
        const uint32_t aB = sbase + (uint32_t)(st * A2SZ) * 2;
        const uint32_t bB = sbase + (uint32_t)(ST2 * A2SZ + st * B2SZ) * 2;
        #pragma unroll
        for (int kk = 0; kk < BK2; kk += 16) {
            uint32_t af[2][4];
            #pragma unroll
            for (int mt = 0; mt < 2; mt++)
                ldsm4(af[mt], aB + aRowOff + (uint32_t)(mt * 16 * LDH2 + kk) * 2);
            #pragma unroll
            for (int ntp = 0; ntp < 4; ntp++) {
                uint32_t bf[4];
                ldsm4t(bf, bB + bAddrOff + (uint32_t)(kk * LDB2 + ntp * 16) * 2);
                #pragma unroll
                for (int mt = 0; mt < 2; mt++) {
                    mma_f16(acc[mt][ntp * 2 + 0], af[mt], bf + 0);
                    mma_f16(acc[mt][ntp * 2 + 1], af[mt], bf + 2);
                }
            }
        }
    }

    __half* T = tiles + OFF_T;
    #pragma unroll
    for (int mt = 0; mt < 2; mt++) {
        #pragma unroll
        for (int nt = 0; nt < 8; nt++) {
            int col = wn + nt * 8 + 2 * tig;
            float bx = b2[col], by = b2[col + 1];
            float v0 = fmaxf(acc[mt][nt][0] + bx, 0.f), v1 = fmaxf(acc[mt][nt][1] + by, 0.f);
            float v2 = fmaxf(acc[mt][nt][2] + bx, 0.f), v3 = fmaxf(acc[mt][nt][3] + by, 0.f);
            int r0 = wm + mt * 16 + gid;
            *(__half2*)&T[r0 * LDT + col]       = __floats2half2_rn(v0, v1);
            *(__half2*)&T[(r0 + 8) * LDT + col] = __floats2half2_rn(v2, v3);
        }
    }
    CPA_WAIT0();
    __syncthreads();

    const int wm3 = (wid & 1) * 32;
    const int wn3 = (wid >> 1) * 32;
    const uint32_t tBase  = sbase + (uint32_t)OFF_T * 2;
    const uint32_t w3Base = sbase + (uint32_t)OFF_W3 * 2;
    const uint32_t aOff3 = (uint32_t)((wm3 + (lane & 15)) * LDT + ((lane >> 4) * 8)) * 2;
    const uint32_t bOff3 = (uint32_t)(((lane & 7) + ((lane >> 3) & 1) * 8) * LDW3
                                      + wn3 + (lane >> 4) * 8) * 2;

    float a3[2][4][4];
    #pragma unroll
    for (int mt = 0; mt < 2; mt++)
        #pragma unroll
        for (int nt = 0; nt < 4; nt++)
            #pragma unroll
            for (int i = 0; i < 4; i++) a3[mt][nt][i] = 0.f;

    #pragma unroll
    for (int kk = 0; kk < 256; kk += 16) {
        uint32_t af[2][4];
        #pragma unroll
        for (int mt = 0; mt < 2; mt++)
            ldsm4(af[mt], tBase + aOff3 + (uint32_t)(mt * 16 * LDT + kk) * 2);
        #pragma unroll
        for (int ntp = 0; ntp < 2; ntp++) {
            uint32_t bf[4];
            ldsm4t(bf, w3Base + bOff3 + (uint32_t)(kk * LDW3 + ntp * 16) * 2);
            #pragma unroll
            for (int mt = 0; mt < 2; mt++) {
                mma_f16(a3[mt][ntp * 2 + 0], af[mt], bf + 0);
                mma_f16(a3[mt][ntp * 2 + 1], af[mt], bf + 2);
            }
        }
    }
    __syncthreads();

    if (!center) {
        // domain: stage half, scatter-store hd, release flags
        __half* stage = tiles;
        #pragma unroll
        for (int mt = 0; mt < 2; mt++) {
            #pragma unroll
            for (int nt = 0; nt < 4; nt++) {
                int col = wn3 + nt * 8 + 2 * tig;
                float bx = b3[col], by = b3[col + 1];
                int r0 = wm3 + mt * 16 + gid;
                *(__half2*)&stage[r0 * 136 + col]       = __floats2half2_rn(a3[mt][nt][0] + bx, a3[mt][nt][1] + by);
                *(__half2*)&stage[(r0 + 8) * 136 + col] = __floats2half2_rn(a3[mt][nt][2] + bx, a3[mt][nt][3] + by);
            }
        }
        __syncthreads();
        #pragma unroll
        for (int i = 0; i < 4; i++) {
            int idx = tid + 256 * i;
            int r = idx >> 4, c8 = (idx & 15) * 8;
            if (m0 + r < cnt) {
                uint4 v = *(uint4*)&stage[r * 136 + c8];
                *(uint4*)&Cd[(size_t)rowC[r] * 128 + c8] = v;
            }
        }
        __threadfence();
        __syncthreads();
        if (tid < 64 && m0 + tid < cnt) atomicExch(&g_flag[rowC[tid]], 1);
        return;
    }

    // ---- center: final fusion + MLP in-CTA (hc never leaves the SM) --------
    float* fbase = (float*)tiles;              // ring region (88 KB) now free
    float* sW1f  = fbase;                      // [j][n] 128x64 = 8192
    float* hcst  = fbase + 8192;               // [64][132]
    float* sW2s  = fbase + 8192 + 64 * 132;    // 64
    float* sb1s  = sW2s + 64;                  // 64
    float* ffuse = sb1s + 64;                  // [8 warps][2][132]

    {
        uint32_t w1a = smem_u32(sW1f);
        #pragma unroll
        for (int i = 0; i < 8; i++) {
            int s = tid + 256 * i;
            cpa16(w1a + (uint32_t)s * 16, fW1 + s * 4);
        }
        CPA_COMMIT();
    }
    if (tid < 64) { sW2s[tid] = fW2[tid]; sb1s[tid] = fb1[tid]; }

    // stage hc (fp32) into smem
    #pragma unroll
    for (int mt = 0; mt < 2; mt++) {
        #pragma unroll
        for (int nt = 0; nt < 4; nt++) {
            int col = wn3 + nt * 8 + 2 * tig;
            float bx = b3[col], by = b3[col + 1];
            int r0 = wm3 + mt * 16 + gid;
            hcst[r0 * 132 + col]           = a3[mt][nt][0] + bx;
            hcst[r0 * 132 + col + 1]       = a3[mt][nt][1] + by;
            hcst[(r0 + 8) * 132 + col]     = a3[mt][nt][2] + bx;
            hcst[(r0 + 8) * 132 + col + 1] = a3[mt][nt][3] + by;
        }
    }

    // wait for the domain producers of our 64 rows
    if (tid < 64) {
        while (atomicAdd(&g_flag[m0 + tid], 0) == 0) __nanosleep(64);
    }
    __threadfence();
    CPA_WAIT0();
    __syncthreads();

    const float fb2v = fb2[0];
    #pragma unroll
    for (int pass = 0; pass < 4; pass++) {
        int rl0 = wid * 8 + pass * 2;
        int rl1 = rl0 + 1;
        float* fr0 = ffuse + (wid * 2 + 0) * 132;
        float* fr1 = ffuse + (wid * 2 + 1) * 132;
        {
            uint2 hdv0 = *(const uint2*)&g_hd[(size_t)(m0 + rl0) * 128 + lane * 4];
            uint2 hdv1 = *(const uint2*)&g_hd[(size_t)(m0 + rl1) * 128 + lane * 4];
            __half2 d00 = *(__half2*)&hdv0.x, d01 = *(__half2*)&hdv0.y;
            __half2 d10 = *(__half2*)&hdv1.x, d11 = *(__half2*)&hdv1.y;
            float2 f00 = __half22float2(d00), f01 = __half22float2(d01);
            float2 f10 = __half22float2(d10), f11 = __half22float2(d11);
            float4 hc0 = *(const float4*)&hcst[rl0 * 132 + lane * 4];
            float4 hc1 = *(const float4*)&hcst[rl1 * 132 + lane * 4];
            float4 o0, o1;
            o0.x = hc0.x * tanhf(f00.x); o0.y = hc0.y * tanhf(f00.y);
            o0.z = hc0.z * tanhf(f01.x); o0.w = hc0.w * tanhf(f01.y);
            o1.x = hc1.x * tanhf(f10.x); o1.y = hc1.y * tanhf(f10.y);
            o1.z = hc1.z * tanhf(f11.x); o1.w = hc1.w * tanhf(f11.y);
            *(float4*)(fr0 + lane * 4) = o0;
            *(float4*)(fr1 + lane * 4) = o1;
        }
        __syncwarp();

        float a00 = 0.f, a01 = 0.f, a10 = 0.f, a11 = 0.f;
        #pragma unroll 4
        for (int jq = 0; jq < 32; jq++) {
            float4 v0 = *(const float4*)(fr0 + jq * 4);
            float4 v1 = *(const float4*)(fr1 + jq * 4);
            float w0a = sW1f[(jq * 4 + 0) * 64 + lane];
            float w1a = sW1f[(jq * 4 + 1) * 64 + lane];
            float w2a = sW1f[(jq * 4 + 2) * 64 + lane];
            float w3a = sW1f[(jq * 4 + 3) * 64 + lane];
            float w0b = sW1f[(jq * 4 + 0) * 64 + lane + 32];
            float w1b = sW1f[(jq * 4 + 1) * 64 + lane + 32];
            float w2b = sW1f[(jq * 4 + 2) * 64 + lane + 32];
            float w3b = sW1f[(jq * 4 + 3) * 64 + lane + 32];
            a00 = fmaf(v0.x, w0a, fmaf(v0.y, w1a, fmaf(v0.z, w2a, fmaf(v0.w, w3a, a00))));
            a01 = fmaf(v0.x, w0b, fmaf(v0.y, w1b, fmaf(v0.z, w2b, fmaf(v0.w, w3b, a01))));
            a10 = fmaf(v1.x, w0a, fmaf(v1.y, w1a, fmaf(v1.z, w2a, fmaf(v1.w, w3a, a10))));
            a11 = fmaf(v1.x, w0b, fmaf(v1.y, w1b, fmaf(v1.z, w2b, fmaf(v1.w, w3b, a11))));
        }
        {
            float s0 = a00 + sb1s[lane];
            float s1 = a01 + sb1s[lane + 32];
            float part = fmaxf(s0, 0.f) * sW2s[lane] + fmaxf(s1, 0.f) * sW2s[lane + 32];
            #pragma unroll
            for (int o = 16; o; o >>= 1) part += __shfl_down_sync(0xffffffffu, part, o);
            if (lane == 0) {
                int r = m0 + rl0;
                out[r] = 1.f / (1.f + expf(-(part + fb2v + g_aux[r])));
            }
        }
        {
            float s0 = a10 + sb1s[lane];
            float s1 = a11 + sb1s[lane + 32];
            float part = fmaxf(s0, 0.f) * sW2s[lane] + fmaxf(s1, 0.f) * sW2s[lane + 32];
            #pragma unroll
            for (int o = 16; o; o >>= 1) part += __shfl_down_sync(0xffffffffu, part, o);
            if (lane == 0) {
                int r = m0 + rl1;
                out[r] = 1.f / (1.f + expf(-(part + fb2v + g_aux[r])));
            }
        }
        __syncwarp();
    }
}

// ---------------- launch -----------------------------------------------------
extern "C" void kernel_launch(void* const* d_in, const int* in_sizes, int n_in,
                              void* d_out, int out_size)
{
    const float* x    = (const float*)d_in[0];
    const int*   dom  = (const int*)  d_in[1];
    const float* pnw  = (const float*)d_in[2];
    const float* pnb  = (const float*)d_in[3];
    const float* demb = (const float*)d_in[4];
    const float* cw   = (const float*)d_in[5];
    const float* cb   = (const float*)d_in[6];
    const float* cW1  = (const float*)d_in[7];
    const float* cb1  = (const float*)d_in[8];
    const float* cW2  = (const float*)d_in[9];
    const float* cb2  = (const float*)d_in[10];
    const float* cW3  = (const float*)d_in[11];
    const float* cb3  = (const float*)d_in[12];
    const float* dW1  = (const float*)d_in[13];
    const float* db1  = (const float*)d_in[14];
    const float* dW2  = (const float*)d_in[15];
    const float* db2  = (const float*)d_in[16];
    const float* dW3  = (const float*)d_in[17];
    const float* db3  = (const float*)d_in[18];
    const float* fW1  = (const float*)d_in[19];
    const float* fb1  = (const float*)d_in[20];
    const float* fW2  = (const float*)d_in[21];
    const float* fb2  = (const float*)d_in[22];
    const float* aW1  = (const float*)d_in[23];
    const float* ab1  = (const float*)d_in[24];
    const float* aW2  = (const float*)d_in[25];
    const float* ab2  = (const float*)d_in[26];
    float* out = (float*)d_out;

    __half *xcP, *ch1P, *dg1P, *hdP;
    __half *wh1cP, *wh1dP, *wh2cP, *wh2dP, *wh3cP, *wh3dP;
    cudaGetSymbolAddress((void**)&xcP,  g_xc);
    cudaGetSymbolAddress((void**)&ch1P, g_ch1);
    cudaGetSymbolAddress((void**)&dg1P, g_dg1);
    cudaGetSymbolAddress((void**)&hdP,  g_hd);
    cudaGetSymbolAddress((void**)&wh1cP, g_wh1c);
    cudaGetSymbolAddress((void**)&wh1dP, g_wh1d);
    cudaGetSymbolAddress((void**)&wh2cP, g_wh2c);
    cudaGetSymbolAddress((void**)&wh2dP, g_wh2d);
    cudaGetSymbolAddress((void**)&wh3cP, g_wh3c);
    cudaGetSymbolAddress((void**)&wh3dP, g_wh3d);

    cudaFuncSetAttribute(gemm_f16<K1P, 512, true, 1>, cudaFuncAttributeMaxDynamicSharedMemorySize, DYNSM);
    cudaFuncSetAttribute(gemm23, cudaFuncAttributeMaxDynamicSharedMemorySize, DYNSM23);

    // single front-end launch: prep + weight convert + partition + flag reset
    k_front<<<FRONT_BLOCKS, 256>>>(x, dom, pnw, pnb, demb, cw, cb,
                                   aW1, ab1, aW2, ab2,
                                   cW1, dW1, cW2, dW2, cW3, dW3);

    // layer 1: K=1088(padded) -> N=512 ; z=0 center, z=1..8 domains
    gemm_f16<K1P, 512, true, 1><<<dim3(4, 32, 9), 256, DYNSM>>>(xcP, xcP, wh1cP, wh1dP, cb1, db1, ch1P, dg1P);
    // fused layers 2+3 + STAR fusion + final MLP (domains z=0..7, center z=8)
    gemm23<<<dim3(1, 64, 9), 256, DYNSM23>>>(ch1P, dg1P, wh2cP, wh2dP, cb2, db2,
                                             wh3cP, wh3dP, cb3, db3, hdP,
                                             fW1, fb1, fW2, fb2, out);
}

// round 17
// speedup vs baseline: 1.1772x; 1.1772x over previous
#include <cuda_runtime.h>
#include <cuda_fp16.h>
#include <cstdint>
#include <math.h>

#define Bsz 4096
#define Ff  1024
#define Ee  16
#define Dd  8
#define Tt  1040
#define Ll  3
#define K1P 1088   // padded K for layer 1 (multiple of 64)

// ---------------- scratch (device globals; no allocation allowed) ----------
__device__ __align__(128) __half g_xc [Bsz*K1P];
__device__ __align__(128) __half g_ch1[Bsz*512];
__device__ __align__(128) __half g_hc [Bsz*128];
__device__ __align__(128) __half g_dg1[Bsz*512];
__device__ __align__(128) __half g_hd [Bsz*128];
__device__ __align__(128) __half g_wh1c[K1P*512];
__device__ __align__(128) __half g_wh1d[Dd*K1P*512];
__device__ __align__(128) __half g_wh2c[512*256];
__device__ __align__(128) __half g_wh2d[Dd*512*256];
__device__ __align__(128) __half g_wh3c[256*128];
__device__ __align__(128) __half g_wh3d[Dd*256*128];
__device__ float g_aux[Bsz];
__device__ int   g_cnt[Dd];
__device__ int   g_off[Dd];
__device__ int   g_perm[Bsz];

// ---------------- PTX helpers ----------------------------------------------
__device__ __forceinline__ uint32_t smem_u32(const void* p) {
    uint32_t a;
    asm("{ .reg .u64 t; cvta.to.shared.u64 t, %1; cvt.u32.u64 %0, t; }" : "=r"(a) : "l"(p));
    return a;
}
__device__ __forceinline__ void ldsm4(uint32_t* r, uint32_t addr) {
    asm volatile("ldmatrix.sync.aligned.m8n8.x4.shared.b16 {%0,%1,%2,%3}, [%4];"
        : "=r"(r[0]), "=r"(r[1]), "=r"(r[2]), "=r"(r[3]) : "r"(addr));
}
__device__ __forceinline__ void ldsm4t(uint32_t* r, uint32_t addr) {
    asm volatile("ldmatrix.sync.aligned.m8n8.x4.trans.shared.b16 {%0,%1,%2,%3}, [%4];"
        : "=r"(r[0]), "=r"(r[1]), "=r"(r[2]), "=r"(r[3]) : "r"(addr));
}
__device__ __forceinline__ void mma_f16(float* c, const uint32_t* a, const uint32_t* b) {
    asm volatile("mma.sync.aligned.m16n8k16.row.col.f32.f16.f16.f32 "
        "{%0,%1,%2,%3}, {%4,%5,%6,%7}, {%8,%9}, {%0,%1,%2,%3};"
        : "+f"(c[0]), "+f"(c[1]), "+f"(c[2]), "+f"(c[3])
        : "r"(a[0]), "r"(a[1]), "r"(a[2]), "r"(a[3]), "r"(b[0]), "r"(b[1]));
}
__device__ __forceinline__ void cpa16(uint32_t dst, const void* src) {
    asm volatile("cp.async.cg.shared.global [%0], [%1], 16;" :: "r"(dst), "l"(src) : "memory");
}
#define CPA_COMMIT() asm volatile("cp.async.commit_group;" ::: "memory")
#define CPA_WAIT1()  asm volatile("cp.async.wait_group 1;" ::: "memory")
#define CPA_WAIT2()  asm volatile("cp.async.wait_group 2;" ::: "memory")
#define CPA_WAIT0()  asm volatile("cp.async.wait_group 0;" ::: "memory")

// ---------------- cvt segment (compile-time divisors) ------------------------
template<int KIN, int KPAD, int N>
__device__ __forceinline__ void cvt_seg(const float* __restrict__ src,
                                        __half* __restrict__ dst, size_t off)
{
    constexpr size_t per = (size_t)KPAD * N;
    int d = (int)(off / per);
    size_t r = off % per;
    int k = (int)(r / N), n = (int)(r % N);
    uint4 u;
    if (k < KIN) {
        const float* s = src + ((size_t)d * KIN + k) * N + n;
        float4 f0 = *(const float4*)s;
        float4 f1 = *(const float4*)(s + 4);
        __half2 h0 = __floats2half2_rn(f0.x, f0.y), h1 = __floats2half2_rn(f0.z, f0.w);
        __half2 h2 = __floats2half2_rn(f1.x, f1.y), h3 = __floats2half2_rn(f1.z, f1.w);
        u.x = *(uint32_t*)&h0; u.y = *(uint32_t*)&h1;
        u.z = *(uint32_t*)&h2; u.w = *(uint32_t*)&h3;
    } else {
        u = make_uint4(0, 0, 0, 0);
    }
    *(uint4*)(dst + off) = u;
}

// ---------------- k_front: warp-per-row prep + cvt + partition ---------------
#define PREP_BLOCKS (Bsz / 8)      // 512: 8 warps/block, 1 row/warp
#define CVT_BLOCKS  3168
#define FRONT_BLOCKS (PREP_BLOCKS + CVT_BLOCKS + 1)

__global__ __launch_bounds__(256)
void k_front(const float* __restrict__ x, const int* __restrict__ dom,
             const float* __restrict__ pnw, const float* __restrict__ pnb,
             const float* __restrict__ demb,
             const float* __restrict__ cw, const float* __restrict__ cb,
             const float* __restrict__ aW1, const float* __restrict__ ab1,
             const float* __restrict__ aW2, const float* __restrict__ ab2,
             const float* __restrict__ cW1, const float* __restrict__ dW1,
             const float* __restrict__ cW2, const float* __restrict__ dW2,
             const float* __restrict__ cW3, const float* __restrict__ dW3)
{
    const int bid = blockIdx.x;
    const int tid = threadIdx.x;

    if (bid >= PREP_BLOCKS) {
        if (bid == PREP_BLOCKS + CVT_BLOCKS) {
            __shared__ int scnt[Dd], soff[Dd], scur[Dd];
            if (tid < Dd) { scnt[tid] = 0; scur[tid] = 0; }
            __syncthreads();
            int dv[16];
            #pragma unroll
            for (int i = 0; i < 16; i++) { dv[i] = dom[tid + 256 * i]; atomicAdd(&scnt[dv[i]], 1); }
            __syncthreads();
            if (tid == 0) {
                int s = 0;
                for (int d = 0; d < Dd; d++) { soff[d] = s; g_off[d] = s; g_cnt[d] = scnt[d]; s += scnt[d]; }
            }
            __syncthreads();
            #pragma unroll
            for (int i = 0; i < 16; i++) {
                int p = atomicAdd(&scur[dv[i]], 1);
                g_perm[soff[dv[i]] + p] = tid + 256 * i;
            }
            return;
        }
        // ---- weight convert (constant divisors per segment) ----
        size_t idx = ((size_t)(bid - PREP_BLOCKS) * 256 + tid) * 8;
        if      (idx < 557056)  cvt_seg<Tt,  K1P, 512>(cW1, g_wh1c, idx);
        else if (idx < 5013504) cvt_seg<Tt,  K1P, 512>(dW1, g_wh1d, idx - 557056);
        else if (idx < 5144576) cvt_seg<512, 512, 256>(cW2, g_wh2c, idx - 5013504);
        else if (idx < 6193152) cvt_seg<512, 512, 256>(dW2, g_wh2d, idx - 5144576);
        else if (idx < 6225920) cvt_seg<256, 256, 128>(cW3, g_wh3c, idx - 6193152);
        else                    cvt_seg<256, 256, 128>(dW3, g_wh3d, idx - 6225920);
        return;
    }

    // ---- prep: ONE ROW PER WARP, all reductions via shuffles --------------
    const int wid  = tid >> 5;
    const int lane = tid & 31;
    const int r = bid * 8 + wid;
    const float* xr = x + (size_t)r * Ff;

    float4 x0v[8], xcv[8];
    float sum = 0.f, sq = 0.f;
    #pragma unroll
    for (int i = 0; i < 8; i++) {
        x0v[i] = *(const float4*)(xr + (i * 32 + lane) * 4);
        sum += x0v[i].x + x0v[i].y + x0v[i].z + x0v[i].w;
        sq  += x0v[i].x * x0v[i].x + x0v[i].y * x0v[i].y
             + x0v[i].z * x0v[i].z + x0v[i].w * x0v[i].w;
    }
    #pragma unroll
    for (int o = 16; o; o >>= 1) {
        sum += __shfl_xor_sync(0xffffffffu, sum, o);
        sq  += __shfl_xor_sync(0xffffffffu, sq, o);
    }
    float mean = sum * (1.f / Ff);
    float var  = sq * (1.f / Ff) - mean * mean;
    float rstd = rsqrtf(var + 1e-5f);

    const int d = dom[r];
    const float* wr = pnw + (size_t)d * Ff;
    const float* br = pnb + (size_t)d * Ff;
    #pragma unroll
    for (int i = 0; i < 8; i++) {
        float4 wv = *(const float4*)(wr + (i * 32 + lane) * 4);
        float4 bv = *(const float4*)(br + (i * 32 + lane) * 4);
        x0v[i].x = (x0v[i].x - mean) * rstd * wv.x + bv.x;
        x0v[i].y = (x0v[i].y - mean) * rstd * wv.y + bv.y;
        x0v[i].z = (x0v[i].z - mean) * rstd * wv.z + bv.z;
        x0v[i].w = (x0v[i].w - mean) * rstd * wv.w + bv.w;
        xcv[i] = x0v[i];
    }
    float x0t = (lane < Ee) ? demb[d * Ee + lane] : 0.f;
    float xct = x0t;

    #pragma unroll
    for (int l = 0; l < Ll; l++) {
        const float* wi = cw + l * Tt;
        const float* bi = cb + l * Tt;
        float p = 0.f;
        #pragma unroll
        for (int i = 0; i < 8; i++) {
            float4 wv = *(const float4*)(wi + (i * 32 + lane) * 4);
            p += xcv[i].x * wv.x + xcv[i].y * wv.y + xcv[i].z * wv.z + xcv[i].w * wv.w;
        }
        if (lane < Ee) p += xct * wi[Ff + lane];
        #pragma unroll
        for (int o = 16; o; o >>= 1) p += __shfl_xor_sync(0xffffffffu, p, o);
        float proj = p;
        #pragma unroll
        for (int i = 0; i < 8; i++) {
            float4 bv = *(const float4*)(bi + (i * 32 + lane) * 4);
            xcv[i].x = fmaf(x0v[i].x, proj, bv.x + xcv[i].x);
            xcv[i].y = fmaf(x0v[i].y, proj, bv.y + xcv[i].y);
            xcv[i].z = fmaf(x0v[i].z, proj, bv.z + xcv[i].z);
            xcv[i].w = fmaf(x0v[i].w, proj, bv.w + xcv[i].w);
        }
        if (lane < Ee) xct = fmaf(x0t, proj, bi[Ff + lane] + xct);
    }

    __half* outp = g_xc + (size_t)r * K1P;
    #pragma unroll
    for (int i = 0; i < 8; i++) {
        __half2 h0 = __floats2half2_rn(xcv[i].x, xcv[i].y);
        __half2 h1 = __floats2half2_rn(xcv[i].z, xcv[i].w);
        uint2 u; u.x = *(uint32_t*)&h0; u.y = *(uint32_t*)&h1;
        *(uint2*)(outp + (i * 32 + lane) * 4) = u;
    }
    if (lane < Ee) outp[Ff + lane] = __float2half_rn(xct);
    #pragma unroll
    for (int j = lane; j < K1P - Tt; j += 32) outp[Tt + j] = __float2half_rn(0.f);

    // aux net: emb values broadcast via shuffles
    {
        float s = ab1[lane];
        #pragma unroll
        for (int e = 0; e < Ee; e++) {
            float xe = __shfl_sync(0xffffffffu, x0t, e);
            s = fmaf(xe, aW1[e * 32 + lane], s);
        }
        s = fmaxf(s, 0.f) * aW2[lane];
        #pragma unroll
        for (int o = 16; o; o >>= 1) s += __shfl_down_sync(0xffffffffu, s, o);
        if (lane == 0) g_aux[r] = s + ab2[0];
    }
}

// ---------------- layer-1 GEMM (8 warps, 64x32 tiles, BK=64, 3 stages) ------
#define BK     64
#define LDH    72
#define LDB    136
#define ASZ    (128*LDH)
#define BSZ    (BK*LDB)
#define STAGES 3
#define DYNSM  (STAGES*(ASZ+BSZ)*2)   // 107520 bytes

template<int K, int N, bool RELU, int LAYER>
__global__ __launch_bounds__(256, 2)
void gemm_f16(const __half* __restrict__ Ac, const __half* __restrict__ Ad,
              const __half* __restrict__ Wc, const __half* __restrict__ Wd,
              const float* __restrict__ bc, const float* __restrict__ bd,
              __half* __restrict__ Cc, __half* __restrict__ Cd)
{
    extern __shared__ __align__(16) __half tiles[];
    __shared__ int rowA[128], rowC[128];

    const int z  = blockIdx.z;
    const int n0 = blockIdx.x * 128;
    const int m0 = blockIdx.y * 128;

    const __half *A, *W;
    const float* bias;
    __half* C;
    int cnt;
    if (z == 0) { A = Ac; W = Wc; bias = bc; C = Cc; cnt = Bsz; }
    else {
        int d = z - 1;
        cnt = g_cnt[d];
        if (m0 >= cnt) return;
        A = Ad; W = Wd + (size_t)d * K * N; bias = bd + d * N; C = Cd;
    }

    const int tid  = threadIdx.x;
    const int wid  = tid >> 5;
    const int lane = tid & 31;

    if (tid < 128) {
        if (z == 0) { rowA[tid] = m0 + tid; rowC[tid] = m0 + tid; }
        else {
            int off = g_off[z - 1];
            int mm  = min(m0 + tid, cnt - 1);
            int slot = off + mm;
            if (LAYER == 1)      { rowA[tid] = g_perm[slot]; rowC[tid] = slot; }
            else if (LAYER == 2) { rowA[tid] = slot;         rowC[tid] = slot; }
            else                 { rowA[tid] = slot;         rowC[tid] = g_perm[slot]; }
        }
    }
    __syncthreads();

    const __half* aSrc[4];
    const __half* bSrc[4];
    uint32_t aDst[4], bDst[4];
    #pragma unroll
    for (int i = 0; i < 4; i++) {
        int s  = tid + 256 * i;
        int ar = s >> 3, ac8 = (s & 7) * 8;
        aSrc[i] = A + (size_t)rowA[ar] * K + ac8;
        aDst[i] = (uint32_t)(ar * LDH + ac8) * 2;
        int kr = s >> 4, nc8 = (s & 15) * 8;
        bSrc[i] = W + (size_t)kr * N + n0 + nc8;
        bDst[i] = (uint32_t)(kr * LDB + nc8) * 2;
    }

    const uint32_t sbase = smem_u32(tiles);

    const int wm = (wid & 1) * 64;
    const int wn = (wid >> 1) * 32;
    const int gid = lane >> 2, tig = lane & 3;
    const uint32_t aRowOff = (uint32_t)((wm + (lane & 15)) * LDH + ((lane >> 4) * 8)) * 2;
    const uint32_t bAddrOff = (uint32_t)(((lane & 7) + ((lane >> 3) & 1) * 8) * LDB
                                         + wn + (lane >> 4) * 8) * 2;

    float acc[4][4][4];
    #pragma unroll
    for (int mt = 0; mt < 4; mt++)
        #pragma unroll
        for (int nt = 0; nt < 4; nt++)
            #pragma unroll
            for (int i = 0; i < 4; i++) acc[mt][nt][i] = 0.f;

    const int NCH = K / BK;

    auto issue = [&](int c, int st) {
        uint32_t aS = sbase + (uint32_t)(st * ASZ) * 2;
        uint32_t bS = sbase + (uint32_t)(STAGES * ASZ + st * BSZ) * 2;
        int k0 = c * BK;
        #pragma unroll
        for (int i = 0; i < 4; i++) cpa16(aS + aDst[i], aSrc[i] + k0);
        #pragma unroll
        for (int i = 0; i < 4; i++) cpa16(bS + bDst[i], bSrc[i] + (size_t)k0 * N);
    };

    issue(0, 0); CPA_COMMIT();
    issue(1, 1); CPA_COMMIT();

    for (int c = 0; c < NCH; c++) {
        CPA_WAIT1();
        __syncthreads();
        if (c + 2 < NCH) issue(c + 2, (c + 2) % STAGES);
        CPA_COMMIT();

        const int st = c % STAGES;
        const uint32_t aB = sbase + (uint32_t)(st * ASZ) * 2;
        const uint32_t bB = sbase + (uint32_t)(STAGES * ASZ + st * BSZ) * 2;
        #pragma unroll
        for (int kk = 0; kk < BK; kk += 16) {
            uint32_t af[4][4];
            #pragma unroll
            for (int mt = 0; mt < 4; mt++)
                ldsm4(af[mt], aB + aRowOff + (uint32_t)(mt * 16 * LDH + kk) * 2);
            #pragma unroll
            for (int ntp = 0; ntp < 2; ntp++) {
                uint32_t bf[4];
                ldsm4t(bf, bB + bAddrOff + (uint32_t)(kk * LDB + ntp * 16) * 2);
                #pragma unroll
                for (int mt = 0; mt < 4; mt++) {
                    mma_f16(acc[mt][ntp * 2 + 0], af[mt], bf + 0);
                    mma_f16(acc[mt][ntp * 2 + 1], af[mt], bf + 2);
                }
            }
        }
    }
    __syncthreads();

    __half* stage = tiles;
    #pragma unroll
    for (int mt = 0; mt < 4; mt++) {
        #pragma unroll
        for (int nt = 0; nt < 4; nt++) {
            int col = wn + nt * 8 + 2 * tig;
            float bx = bias[n0 + col], by = bias[n0 + col + 1];
            float v0 = acc[mt][nt][0] + bx, v1 = acc[mt][nt][1] + by;
            float v2 = acc[mt][nt][2] + bx, v3 = acc[mt][nt][3] + by;
            if (RELU) {
                v0 = fmaxf(v0, 0.f); v1 = fmaxf(v1, 0.f);
                v2 = fmaxf(v2, 0.f); v3 = fmaxf(v3, 0.f);
            }
            int r0 = wm + mt * 16 + gid;
            *(__half2*)&stage[r0 * 136 + col]       = __floats2half2_rn(v0, v1);
            *(__half2*)&stage[(r0 + 8) * 136 + col] = __floats2half2_rn(v2, v3);
        }
    }
    __syncthreads();
    #pragma unroll
    for (int i = 0; i < 8; i++) {
        int idx = tid + 256 * i;
        int r = idx >> 4, c8 = (idx & 15) * 8;
        if (z == 0 || m0 + r < cnt) {
            uint4 v = *(uint4*)&stage[r * 136 + c8];
            *(uint4*)&C[(size_t)rowC[r] * N + n0 + c8] = v;
        }
    }
}

// ---------------- fused layers 2+3 (round-15: 4-stage phase-A) --------------
#define BK2   32
#define LDH2  40
#define LDB2  264
#define LDT   264
#define LDW3  136
#define A2SZ  (64*LDH2)
#define B2SZ  (BK2*LDB2)
#define ST2   4
#define OFF_T   (ST2*A2SZ + ST2*B2SZ)
#define OFF_W3  (OFF_T + 64*LDT)
#define DYNSM23 ((OFF_W3 + 256*LDW3) * 2)

__global__ __launch_bounds__(256)
void gemm23(const __half* __restrict__ Ac, const __half* __restrict__ Ad,
            const __half* __restrict__ W2c, const __half* __restrict__ W2d,
            const float* __restrict__ b2c, const float* __restrict__ b2d,
            const __half* __restrict__ W3c, const __half* __restrict__ W3d,
            const float* __restrict__ b3c, const float* __restrict__ b3d,
            __half* __restrict__ Cc, __half* __restrict__ Cd)
{
    extern __shared__ __align__(16) __half tiles[];
    __shared__ int rowA[64], rowC[64];

    const int z  = blockIdx.z;
    const int m0 = blockIdx.y * 64;

    const __half *A, *W2, *W3;
    const float *b2, *b3;
    __half* C;
    int cnt;
    if (z == 0) { A = Ac; W2 = W2c; b2 = b2c; W3 = W3c; b3 = b3c; C = Cc; cnt = Bsz; }
    else {
        int d = z - 1;
        cnt = g_cnt[d];
        if (m0 >= cnt) return;
        A  = Ad;
        W2 = W2d + (size_t)d * 512 * 256; b2 = b2d + d * 256;
        W3 = W3d + (size_t)d * 256 * 128; b3 = b3d + d * 128;
        C  = Cd;
    }

    const int tid  = threadIdx.x;
    const int wid  = tid >> 5;
    const int lane = tid & 31;

    if (tid < 64) {
        if (z == 0) { rowA[tid] = m0 + tid; rowC[tid] = m0 + tid; }
        else {
            int off = g_off[z - 1];
            int mm  = min(m0 + tid, cnt - 1);
            int slot = off + mm;
            rowA[tid] = slot;
            rowC[tid] = g_perm[slot];
        }
    }
    __syncthreads();

    const uint32_t sbase = smem_u32(tiles);

    {
        uint32_t w3S = sbase + (uint32_t)OFF_W3 * 2;
        #pragma unroll
        for (int i = 0; i < 16; i++) {
            int s = tid + 256 * i;
            int kr = s >> 4, nc8 = (s & 15) * 8;
            cpa16(w3S + (uint32_t)(kr * LDW3 + nc8) * 2, W3 + (size_t)kr * 128 + nc8);
        }
        CPA_COMMIT();
    }

    const __half* aSrc = A + (size_t)rowA[tid >> 2] * 512 + (tid & 3) * 8;
    const uint32_t aDst = (uint32_t)((tid >> 2) * LDH2 + (tid & 3) * 8) * 2;
    const __half* bSrc[4];
    uint32_t bDst[4];
    #pragma unroll
    for (int i = 0; i < 4; i++) {
        int s = tid + 256 * i;
        int kr = s >> 5, nc8 = (s & 31) * 8;
        bSrc[i] = W2 + (size_t)kr * 256 + nc8;
        bDst[i] = (uint32_t)(kr * LDB2 + nc8) * 2;
    }

    auto issue = [&](int c, int st) {
        uint32_t aS = sbase + (uint32_t)(st * A2SZ) * 2;
        uint32_t bS = sbase + (uint32_t)(ST2 * A2SZ + st * B2SZ) * 2;
        int k0 = c * BK2;
        cpa16(aS + aDst, aSrc + k0);
        #pragma unroll
        for (int i = 0; i < 4; i++) cpa16(bS + bDst[i], bSrc[i] + (size_t)k0 * 256);
    };

    issue(0, 0); CPA_COMMIT();
    issue(1, 1); CPA_COMMIT();
    issue(2, 2); CPA_COMMIT();

    const int wm = (wid & 1) * 32;
    const int wn = (wid >> 1) * 64;
    const int gid = lane >> 2, tig = lane & 3;
    const uint32_t aRowOff = (uint32_t)((wm + (lane & 15)) * LDH2 + ((lane >> 4) * 8)) * 2;
    const uint32_t bAddrOff = (uint32_t)(((lane & 7) + ((lane >> 3) & 1) * 8) * LDB2
                                         + wn + (lane >> 4) * 8) * 2;

    float acc[2][8][4];
    #pragma unroll
    for (int mt = 0; mt < 2; mt++)
        #pragma unroll
        for (int nt = 0; nt < 8; nt++)
            #pragma unroll
            for (int i = 0; i < 4; i++) acc[mt][nt][i] = 0.f;

    const int NCH = 512 / BK2;
    for (int c = 0; c < NCH; c++) {
        CPA_WAIT2();
        __syncthreads();
        if (c + 3 < NCH) issue(c + 3, (c + 3) % ST2);
        CPA_COMMIT();

        const int st = c % ST2;
        const uint32_t aB = sbase + (uint32_t)(st * A2SZ) * 2;
        const uint32_t bB = sbase + (uint32_t)(ST2 * A2SZ + st * B2SZ) * 2;
        #pragma unroll
        for (int kk = 0; kk < BK2; kk += 16) {
            uint32_t af[2][4];
            #pragma unroll
            for (int mt = 0; mt < 2; mt++)
                ldsm4(af[mt], aB + aRowOff + (uint32_t)(mt * 16 * LDH2 + kk) * 2);
            #pragma unroll
            for (int ntp = 0; ntp < 4; ntp++) {
                uint32_t bf[4];
                ldsm4t(bf, bB + bAddrOff + (uint32_t)(kk * LDB2 + ntp * 16) * 2);
                #pragma unroll
                for (int mt = 0; mt < 2; mt++) {
                    mma_f16(acc[mt][ntp * 2 + 0], af[mt], bf + 0);
                    mma_f16(acc[mt][ntp * 2 + 1], af[mt], bf + 2);
                }
            }
        }
    }

    __half* T = tiles + OFF_T;
    #pragma unroll
    for (int mt = 0; mt < 2; mt++) {
        #pragma unroll
        for (int nt = 0; nt < 8; nt++) {
            int col = wn + nt * 8 + 2 * tig;
            float bx = b2[col], by = b2[col + 1];
            float v0 = fmaxf(acc[mt][nt][0] + bx, 0.f), v1 = fmaxf(acc[mt][nt][1] + by, 0.f);
            float v2 = fmaxf(acc[mt][nt][2] + bx, 0.f), v3 = fmaxf(acc[mt][nt][3] + by, 0.f);
            int r0 = wm + mt * 16 + gid;
            *(__half2*)&T[r0 * LDT + col]       = __floats2half2_rn(v0, v1);
            *(__half2*)&T[(r0 + 8) * LDT + col] = __floats2half2_rn(v2, v3);
        }
    }
    CPA_WAIT0();
    __syncthreads();

    const int wm3 = (wid & 1) * 32;
    const int wn3 = (wid >> 1) * 32;
    const uint32_t tBase  = sbase + (uint32_t)OFF_T * 2;
    const uint32_t w3Base = sbase + (uint32_t)OFF_W3 * 2;
    const uint32_t aOff3 = (uint32_t)((wm3 + (lane & 15)) * LDT + ((lane >> 4) * 8)) * 2;
    const uint32_t bOff3 = (uint32_t)(((lane & 7) + ((lane >> 3) & 1) * 8) * LDW3
                                      + wn3 + (lane >> 4) * 8) * 2;

    float a3[2][4][4];
    #pragma unroll
    for (int mt = 0; mt < 2; mt++)
        #pragma unroll
        for (int nt = 0; nt < 4; nt++)
            #pragma unroll
            for (int i = 0; i < 4; i++) a3[mt][nt][i] = 0.f;

    #pragma unroll
    for (int kk = 0; kk < 256; kk += 16) {
        uint32_t af[2][4];
        #pragma unroll
        for (int mt = 0; mt < 2; mt++)
            ldsm4(af[mt], tBase + aOff3 + (uint32_t)(mt * 16 * LDT + kk) * 2);
        #pragma unroll
        for (int ntp = 0; ntp < 2; ntp++) {
            uint32_t bf[4];
            ldsm4t(bf, w3Base + bOff3 + (uint32_t)(kk * LDW3 + ntp * 16) * 2);
            #pragma unroll
            for (int mt = 0; mt < 2; mt++) {
                mma_f16(a3[mt][ntp * 2 + 0], af[mt], bf + 0);
                mma_f16(a3[mt][ntp * 2 + 1], af[mt], bf + 2);
            }
        }
    }
    __syncthreads();

    __half* stage = tiles;
    #pragma unroll
    for (int mt = 0; mt < 2; mt++) {
        #pragma unroll
        for (int nt = 0; nt < 4; nt++) {
            int col = wn3 + nt * 8 + 2 * tig;
            float bx = b3[col], by = b3[col + 1];
            float v0 = a3[mt][nt][0] + bx, v1 = a3[mt][nt][1] + by;
            float v2 = a3[mt][nt][2] + bx, v3 = a3[mt][nt][3] + by;
            int r0 = wm3 + mt * 16 + gid;
            *(__half2*)&stage[r0 * 136 + col]       = __floats2half2_rn(v0, v1);
            *(__half2*)&stage[(r0 + 8) * 136 + col] = __floats2half2_rn(v2, v3);
        }
    }
    __syncthreads();
    #pragma unroll
    for (int i = 0; i < 4; i++) {
        int idx = tid + 256 * i;
        int r = idx >> 4, c8 = (idx & 15) * 8;
        if (z == 0 || m0 + r < cnt) {
            uint4 v = *(uint4*)&stage[r * 136 + c8];
            *(uint4*)&C[(size_t)rowC[r] * 128 + c8] = v;
        }
    }
}

// ---------------- K_final (round-13: 256 blocks x 16 rows) ------------------
#define KF_ROWS 16

__global__ __launch_bounds__(256)
void k_final(const float* __restrict__ fW1, const float* __restrict__ fb1,
             const float* __restrict__ fW2, const float* __restrict__ fb2,
             float* __restrict__ out)
{
    __shared__ __align__(16) float sW1[128 * 64];
    __shared__ float sfused[KF_ROWS][132];
    __shared__ float sW2[64], sb1[64];

    const int tid  = threadIdx.x;
    const int wid  = tid >> 5;
    const int lane = tid & 31;

    {
        uint32_t sw1a = smem_u32(sW1);
        #pragma unroll
        for (int i = 0; i < 8; i++) {
            int s = tid + 256 * i;
            cpa16(sw1a + (uint32_t)s * 16, fW1 + s * 4);
        }
        CPA_COMMIT();
    }
    if (tid < 64) { sW2[tid] = fW2[tid]; sb1[tid] = fb1[tid]; }

    const int rbase = blockIdx.x * KF_ROWS;
    #pragma unroll
    for (int rr = 0; rr < 2; rr++) {
        int rloc = wid * 2 + rr;
        int r = rbase + rloc;
        uint2 hcv = *(const uint2*)&g_hc[r * 128 + lane * 4];
        uint2 hdv = *(const uint2*)&g_hd[r * 128 + lane * 4];
        __half2 c0 = *(__half2*)&hcv.x, c1 = *(__half2*)&hcv.y;
        __half2 d0 = *(__half2*)&hdv.x, d1 = *(__half2*)&hdv.y;
        float2 cf0 = __half22float2(c0), cf1 = __half22float2(c1);
        float2 df0 = __half22float2(d0), df1 = __half22float2(d1);
        sfused[rloc][lane * 4 + 0] = cf0.x * tanhf(df0.x);
        sfused[rloc][lane * 4 + 1] = cf0.y * tanhf(df0.y);
        sfused[rloc][lane * 4 + 2] = cf1.x * tanhf(df1.x);
        sfused[rloc][lane * 4 + 3] = cf1.y * tanhf(df1.y);
    }
    CPA_WAIT0();
    __syncthreads();

    float a00 = 0.f, a01 = 0.f, a10 = 0.f, a11 = 0.f;
    const float* f0 = sfused[wid * 2 + 0];
    const float* f1 = sfused[wid * 2 + 1];

    #pragma unroll 4
    for (int j4 = 0; j4 < 32; j4++) {
        float4 v0 = *(const float4*)(f0 + j4 * 4);
        float4 v1 = *(const float4*)(f1 + j4 * 4);
        float w0a = sW1[(j4 * 4 + 0) * 64 + lane];
        float w1a = sW1[(j4 * 4 + 1) * 64 + lane];
        float w2a = sW1[(j4 * 4 + 2) * 64 + lane];
        float w3a = sW1[(j4 * 4 + 3) * 64 + lane];
        float w0b = sW1[(j4 * 4 + 0) * 64 + lane + 32];
        float w1b = sW1[(j4 * 4 + 1) * 64 + lane + 32];
        float w2b = sW1[(j4 * 4 + 2) * 64 + lane + 32];
        float w3b = sW1[(j4 * 4 + 3) * 64 + lane + 32];
        a00 = fmaf(v0.x, w0a, fmaf(v0.y, w1a, fmaf(v0.z, w2a, fmaf(v0.w, w3a, a00))));
        a01 = fmaf(v0.x, w0b, fmaf(v0.y, w1b, fmaf(v0.z, w2b, fmaf(v0.w, w3b, a01))));
        a10 = fmaf(v1.x, w0a, fmaf(v1.y, w1a, fmaf(v1.z, w2a, fmaf(v1.w, w3a, a10))));
        a11 = fmaf(v1.x, w0b, fmaf(v1.y, w1b, fmaf(v1.z, w2b, fmaf(v1.w, w3b, a11))));
    }

    const float fb2v = fb2[0];
    {
        float s0 = a00 + sb1[lane];
        float s1 = a01 + sb1[lane + 32];
        float part = fmaxf(s0, 0.f) * sW2[lane] + fmaxf(s1, 0.f) * sW2[lane + 32];
        #pragma unroll
        for (int o = 16; o; o >>= 1) part += __shfl_down_sync(0xffffffffu, part, o);
        if (lane == 0) {
            int r = rbase + wid * 2;
            out[r] = 1.f / (1.f + expf(-(part + fb2v + g_aux[r])));
        }
    }
    {
        float s0 = a10 + sb1[lane];
        float s1 = a11 + sb1[lane + 32];
        float part = fmaxf(s0, 0.f) * sW2[lane] + fmaxf(s1, 0.f) * sW2[lane + 32];
        #pragma unroll
        for (int o = 16; o; o >>= 1) part += __shfl_down_sync(0xffffffffu, part, o);
        if (lane == 0) {
            int r = rbase + wid * 2 + 1;
            out[r] = 1.f / (1.f + expf(-(part + fb2v + g_aux[r])));
        }
    }
}

// ---------------- launch -----------------------------------------------------
extern "C" void kernel_launch(void* const* d_in, const int* in_sizes, int n_in,
                              void* d_out, int out_size)
{
    const float* x    = (const float*)d_in[0];
    const int*   dom  = (const int*)  d_in[1];
    const float* pnw  = (const float*)d_in[2];
    const float* pnb  = (const float*)d_in[3];
    const float* demb = (const float*)d_in[4];
    const float* cw   = (const float*)d_in[5];
    const float* cb   = (const float*)d_in[6];
    const float* cW1  = (const float*)d_in[7];
    const float* cb1  = (const float*)d_in[8];
    const float* cW2  = (const float*)d_in[9];
    const float* cb2  = (const float*)d_in[10];
    const float* cW3  = (const float*)d_in[11];
    const float* cb3  = (const float*)d_in[12];
    const float* dW1  = (const float*)d_in[13];
    const float* db1  = (const float*)d_in[14];
    const float* dW2  = (const float*)d_in[15];
    const float* db2  = (const float*)d_in[16];
    const float* dW3  = (const float*)d_in[17];
    const float* db3  = (const float*)d_in[18];
    const float* fW1  = (const float*)d_in[19];
    const float* fb1  = (const float*)d_in[20];
    const float* fW2  = (const float*)d_in[21];
    const float* fb2  = (const float*)d_in[22];
    const float* aW1  = (const float*)d_in[23];
    const float* ab1  = (const float*)d_in[24];
    const float* aW2  = (const float*)d_in[25];
    const float* ab2  = (const float*)d_in[26];
    float* out = (float*)d_out;

    __half *xcP, *ch1P, *hcP, *dg1P, *hdP;
    __half *wh1cP, *wh1dP, *wh2cP, *wh2dP, *wh3cP, *wh3dP;
    cudaGetSymbolAddress((void**)&xcP,  g_xc);
    cudaGetSymbolAddress((void**)&ch1P, g_ch1);
    cudaGetSymbolAddress((void**)&hcP,  g_hc);
    cudaGetSymbolAddress((void**)&dg1P, g_dg1);
    cudaGetSymbolAddress((void**)&hdP,  g_hd);
    cudaGetSymbolAddress((void**)&wh1cP, g_wh1c);
    cudaGetSymbolAddress((void**)&wh1dP, g_wh1d);
    cudaGetSymbolAddress((void**)&wh2cP, g_wh2c);
    cudaGetSymbolAddress((void**)&wh2dP, g_wh2d);
    cudaGetSymbolAddress((void**)&wh3cP, g_wh3c);
    cudaGetSymbolAddress((void**)&wh3dP, g_wh3d);

    cudaFuncSetAttribute(gemm_f16<K1P, 512, true, 1>, cudaFuncAttributeMaxDynamicSharedMemorySize, DYNSM);
    cudaFuncSetAttribute(gemm23, cudaFuncAttributeMaxDynamicSharedMemorySize, DYNSM23);

    // single front-end launch: warp-per-row prep + weight convert + partition
    k_front<<<FRONT_BLOCKS, 256>>>(x, dom, pnw, pnb, demb, cw, cb,
                                   aW1, ab1, aW2, ab2,
                                   cW1, dW1, cW2, dW2, cW3, dW3);

    // layer 1: K=1088(padded) -> N=512 ; z=0 center, z=1..8 domains
    gemm_f16<K1P, 512, true, 1><<<dim3(4, 32, 9), 256, DYNSM>>>(xcP, xcP, wh1cP, wh1dP, cb1, db1, ch1P, dg1P);
    // fused layers 2+3
    gemm23<<<dim3(1, 64, 9), 256, DYNSM23>>>(ch1P, dg1P, wh2cP, wh2dP, cb2, db2,
                                             wh3cP, wh3dP, cb3, db3, hcP, hdP);

    k_final<<<Bsz / KF_ROWS, 256>>>(fW1, fb1, fW2, fb2, out);
}